// round 10
// baseline (speedup 1.0000x reference)
#include <cuda_runtime.h>
#include <math.h>
#include <stdint.h>

#define H 2048
#define E 64
#define S 4096
#define B 2
#define SW 1024
#define NEGF (-3.4028234663852886e38f)   // -FLT_MAX == finfo(float32).min

#define OFF_SLID 33554432ull             // 2*4096*4096
#define OFF_W    67108864ull
#define OFF_I    67141632ull             // OFF_W + 8192*4

#define RSQRT_H 0.022097086912079608f    // 1/sqrt(2048)
#define KT 32                            // k-tile
#define XPAD 68                          // X row stride (floats)
#define WPAD 132                         // W dup row stride (floats): 128 dup + 4
#define NKT (H / KT)                     // 64
#define XTILE_F (KT * XPAD)              // 2176
#define WTILE_F (KT * WPAD)              // 4224
#define FOLD_BLOCKS 128

// dynamic smem layout (floats):
//   X stages:  [0, 2*XTILE_F)            = 4352 floats (17408 B)
//   W stages:  [2*XTILE_F, +2*WTILE_F)   = 8448 floats (33792 B)
//   s_l[64][68] aliases the X region (exactly 4352 floats)
#define GATE_SMEM_BYTES ((2 * XTILE_F + 2 * WTILE_F) * 4)

// scratch (no allocations allowed)
__device__ int4  g_qmeta[B * S];                        // {flo, s1lo, v2lo, v2hi}
__device__ __align__(16) float g_w2t[NKT * WTILE_F];    // folded W, duplicated pairs

// ---------------------------------------------------------------------------
// cp.async helpers
// ---------------------------------------------------------------------------
#define CP_ASYNC4(dst, src) \
    asm volatile("cp.async.ca.shared.global [%0], [%1], 4;" :: "r"(dst), "l"(src))
#define CP_ASYNC16(dst, src) \
    asm volatile("cp.async.cg.shared.global [%0], [%1], 16;" :: "r"(dst), "l"(src))
#define CP_COMMIT() asm volatile("cp.async.commit_group;")
#define CP_WAIT1()  asm volatile("cp.async.wait_group 1;")

// packed fp32x2 FMA (sm_100+), non-volatile so ptxas can schedule freely
__device__ __forceinline__ void ffma2(unsigned long long& d,
                                      unsigned long long a,
                                      unsigned long long b) {
    asm("fma.rn.f32x2 %0, %1, %2, %0;" : "+l"(d) : "l"(a), "l"(b));
}

// ---------------------------------------------------------------------------
// block-wide exclusive scans for prep (256 threads)
// ---------------------------------------------------------------------------
__device__ __forceinline__ int blk_excl_max(int agg, int t, int* sc) {
    int lane = t & 31, w = t >> 5;
    int inc = agg;
    #pragma unroll
    for (int o = 1; o < 32; o <<= 1) {
        int u = __shfl_up_sync(0xffffffffu, inc, o);
        if (lane >= o) inc = max(inc, u);
    }
    if (lane == 31) sc[w] = inc;
    __syncthreads();
    int wex = -0x7fffffff;
    for (int i = 0; i < w; i++) wex = max(wex, sc[i]);
    int lex = __shfl_up_sync(0xffffffffu, inc, 1);
    if (lane == 0) lex = -0x7fffffff;
    __syncthreads();
    return max(wex, lex);
}

__device__ __forceinline__ int blk_excl_min_bwd(int agg, int t, int* sc) {
    int lane = t & 31, w = t >> 5;
    int inc = agg;
    #pragma unroll
    for (int o = 1; o < 32; o <<= 1) {
        int u = __shfl_down_sync(0xffffffffu, inc, o);
        if (lane < 32 - o) inc = min(inc, u);
    }
    if (lane == 0) sc[w] = inc;
    __syncthreads();
    int wex = 0x7fffffff;
    for (int i = w + 1; i < 8; i++) wex = min(wex, sc[i]);
    int lex = __shfl_down_sync(0xffffffffu, inc, 1);
    if (lane == 31) lex = 0x7fffffff;
    __syncthreads();
    return min(wex, lex);
}

// ---------------------------------------------------------------------------
// K0: fold W into k-major, pair-duplicated tile images (+ 2 prep blocks)
// ---------------------------------------------------------------------------
__global__ __launch_bounds__(256) void foldprep_kernel(const float* __restrict__ scale,
                                                       const float* __restrict__ pw,
                                                       const int* __restrict__ packed,
                                                       const int* __restrict__ mm) {
    if (blockIdx.x < FOLD_BLOCKS) {
        int i = blockIdx.x * 1024 + threadIdx.x * 4;     // over E*H = 131072
        float4 pw4 = *(const float4*)(pw + i);
        float4 sc4 = *(const float4*)(scale + (i & (H - 1)));
        int e  = i >> 11;
        int h  = i & (H - 1);
        int kt = h >> 5, k = h & 31;                     // k % 4 == 0
        float v0 = pw4.x * sc4.x * RSQRT_H;
        float v1 = pw4.y * sc4.y * RSQRT_H;
        float v2 = pw4.z * sc4.z * RSQRT_H;
        float v3 = pw4.w * sc4.w * RSQRT_H;
        float* dst = g_w2t + kt * WTILE_F + k * WPAD + 2 * e;
        *(float2*)(dst + 0 * WPAD) = make_float2(v0, v0);
        *(float2*)(dst + 1 * WPAD) = make_float2(v1, v1);
        *(float2*)(dst + 2 * WPAD) = make_float2(v2, v2);
        *(float2*)(dst + 3 * WPAD) = make_float2(v3, v3);
    } else {
        // ================= PREP =================
        __shared__ int sc[8];
        const int INF = 0x7fffffff;
        int b = blockIdx.x - FOLD_BLOCKS;
        int t = threadIdx.x;
        int base = t * 16;
        const int* pk = packed + b * S;
        const int* m  = mm + b * S;

        int p[16]; bool v[16];
        #pragma unroll
        for (int c = 0; c < 4; c++) {
            int4 pp4 = ((const int4*)(pk + base))[c];
            int4 mm4 = ((const int4*)(m + base))[c];
            p[4*c+0] = pp4.x; p[4*c+1] = pp4.y; p[4*c+2] = pp4.z; p[4*c+3] = pp4.w;
            v[4*c+0] = (mm4.x == 1) | (mm4.x == 2);
            v[4*c+1] = (mm4.y == 1) | (mm4.y == 2);
            v[4*c+2] = (mm4.z == 1) | (mm4.z == 2);
            v[4*c+3] = (mm4.w == 1) | (mm4.w == 2);
        }
        int  pprev = (base > 0) ? pk[base - 1] : -123456;
        int  pnext = (base + 16 < S) ? pk[base + 16] : -123456;
        int  mprev = (base > 0) ? m[base - 1] : 0;
        int  mnext = (base + 16 < S) ? m[base + 16] : 0;
        bool vprev = (mprev == 1) | (mprev == 2);
        bool vnext = (mnext == 1) | (mnext == 2);

        int dloc[16];
        {
            int run = -1, pp = pprev;
            #pragma unroll
            for (int j = 0; j < 16; j++) {
                if (p[j] != pp) run = base + j;
                dloc[j] = run; pp = p[j];
            }
            int ex = blk_excl_max(run, t, sc);
            #pragma unroll
            for (int j = 0; j < 16; j++) if (ex > dloc[j]) dloc[j] = ex;
        }
        int vloc[16];
        {
            int run = -1; bool pv = vprev;
            #pragma unroll
            for (int j = 0; j < 16; j++) {
                if (v[j] && !pv) run = base + j;
                vloc[j] = run; pv = v[j];
            }
            int ex = blk_excl_max(run, t, sc);
            #pragma unroll
            for (int j = 0; j < 16; j++) if (ex > vloc[j]) vloc[j] = ex;
        }
        int dend[16];
        {
            int run = INF, np = pnext;
            #pragma unroll
            for (int jj = 15; jj >= 0; jj--) {
                if (p[jj] != np) run = base + jj;
                dend[jj] = run; np = p[jj];
            }
            int ex = blk_excl_min_bwd(run, t, sc);
            #pragma unroll
            for (int j = 0; j < 16; j++) if (ex < dend[j]) dend[j] = ex;
        }
        int vend[16];
        {
            int run = INF; bool nv = vnext;
            #pragma unroll
            for (int jj = 15; jj >= 0; jj--) {
                if (v[jj] && !nv) run = base + jj;
                vend[jj] = run; nv = v[jj];
            }
            int ex = blk_excl_min_bwd(run, t, sc);
            #pragma unroll
            for (int j = 0; j < 16; j++) if (ex < vend[j]) vend[j] = ex;
        }

        #pragma unroll
        for (int j = 0; j < 16; j++) {
            int q = base + j;
            int4 mt;
            if (p[j] <= 0) {
                mt.x = S; mt.y = S; mt.z = S; mt.w = -1;
            } else {
                int flo = dloc[j];
                mt.x = flo;
                int s1 = q - (SW - 1);
                mt.y = (s1 > flo) ? s1 : flo;
                if (v[j]) {
                    int vl = vloc[j]; if (flo > vl) vl = flo;
                    int vh = vend[j]; if (dend[j] < vh) vh = dend[j];
                    mt.z = vl; mt.w = vh;
                } else {
                    mt.z = S; mt.w = -1;
                }
            }
            g_qmeta[b * S + q] = mt;
        }
    }
}

// ---------------------------------------------------------------------------
// K1: gate. 128 blocks x (64 rows x 64 experts), cp.async 2-stage pipeline,
// f32x2 FMA with pair-duplicated W (no pack movs), fused RMS + top-4.
// ---------------------------------------------------------------------------
__global__ __launch_bounds__(256) void gate_kernel(const float* __restrict__ x,
                                                   float* __restrict__ out) {
    extern __shared__ __align__(16) float dsm[];
    // X stage s: dsm + s*XTILE_F ; W stage s: dsm + 2*XTILE_F + s*WTILE_F
    float (*s_l)[XPAD] = (float (*)[XPAD])dsm;          // aliases X region

    int bm  = blockIdx.x;
    int tid = threadIdx.x;
    int w   = tid >> 5, lane = tid & 31;
    int tr  = tid >> 4, tc = tid & 15;
    const float* xb = x + (size_t)bm * 64 * H;

    uint32_t smb = (uint32_t)__cvta_generic_to_shared(dsm);
    const uint32_t XSTB = (uint32_t)(XTILE_F * 4);
    const uint32_t WSTB = (uint32_t)(WTILE_F * 4);
    uint32_t wbase = smb + 2 * XSTB;

    int lrow = tid >> 5;
    int lk   = tid & 31;
    uint32_t xdst0 = smb + (uint32_t)(lk * XPAD + lrow) * 4u;
    const float* xsrc0 = xb + (size_t)lrow * H + lk;

    // prologue: tile 0 into stage 0
    {
        #pragma unroll
        for (int i = 0; i < 8; i++)
            CP_ASYNC4(xdst0 + (uint32_t)(8 * i) * 4u, xsrc0 + (size_t)(8 * i) * H);
        const float4* wsrc = (const float4*)(g_w2t);
        #pragma unroll
        for (int j = 0; j < 4; j++)
            CP_ASYNC16(wbase + (uint32_t)(tid + j * 256) * 16u, wsrc + tid + j * 256);
        if (tid < 32)
            CP_ASYNC16(wbase + (uint32_t)(tid + 1024) * 16u, wsrc + tid + 1024);
        CP_COMMIT();
    }

    unsigned long long acc[4][2] = {};   // [expert j][row pair p]
    float ssq[8] = {};

    for (int kt = 0; kt < NKT; kt++) {
        int s = kt & 1;
        if (kt + 1 < NKT) {
            int ns = (kt + 1) & 1;
            uint32_t xd = xdst0 + (uint32_t)ns * XSTB;
            const float* xs = xsrc0 + (size_t)(kt + 1) * KT;
            #pragma unroll
            for (int i = 0; i < 8; i++)
                CP_ASYNC4(xd + (uint32_t)(8 * i) * 4u, xs + (size_t)(8 * i) * H);
            const float4* wsrc = (const float4*)(g_w2t + (size_t)(kt + 1) * WTILE_F);
            uint32_t wd = wbase + (uint32_t)ns * WSTB;
            #pragma unroll
            for (int j = 0; j < 4; j++)
                CP_ASYNC16(wd + (uint32_t)(tid + j * 256) * 16u, wsrc + tid + j * 256);
            if (tid < 32)
                CP_ASYNC16(wd + (uint32_t)(tid + 1024) * 16u, wsrc + tid + 1024);
        }
        CP_COMMIT();
        CP_WAIT1();
        __syncthreads();

        const float* Xs = dsm + s * XTILE_F;
        const float* Wsd = dsm + 2 * XTILE_F + s * WTILE_F;
        #pragma unroll
        for (int k = 0; k < KT; k++) {
            ulonglong2 xv = *(const ulonglong2*)(Xs + k * XPAD + 4 * tr);     // {x0,x1},{x2,x3}
            ulonglong2 w01 = *(const ulonglong2*)(Wsd + k * WPAD + 8 * tc);   // {w0,w0},{w1,w1}
            ulonglong2 w23 = *(const ulonglong2*)(Wsd + k * WPAD + 8 * tc + 4);
            ffma2(acc[0][0], xv.x, w01.x); ffma2(acc[0][1], xv.y, w01.x);
            ffma2(acc[1][0], xv.x, w01.y); ffma2(acc[1][1], xv.y, w01.y);
            ffma2(acc[2][0], xv.x, w23.x); ffma2(acc[2][1], xv.y, w23.x);
            ffma2(acc[3][0], xv.x, w23.y); ffma2(acc[3][1], xv.y, w23.y);
        }
        // rms sum-of-squares pass (lane = k, rows w+8i)
        #pragma unroll
        for (int i = 0; i < 8; i++) {
            float v = Xs[lane * XPAD + (w + 8 * i)];
            ssq[i] = fmaf(v, v, ssq[i]);
        }
        __syncthreads();
    }

    // epilogue: logits to smem (aliases X stages — pipeline done)
    #pragma unroll
    for (int j = 0; j < 4; j++) {
        #pragma unroll
        for (int p = 0; p < 2; p++) {
            float lo, hi;
            asm("mov.b64 {%0,%1},%2;" : "=f"(lo), "=f"(hi) : "l"(acc[j][p]));
            s_l[4 * tr + 2 * p][4 * tc + j]     = lo;
            s_l[4 * tr + 2 * p + 1][4 * tc + j] = hi;
        }
    }
    __syncthreads();

    // per-row top-4 + renormalized softmax (== softmax over top-4 logits)
    #pragma unroll
    for (int i = 0; i < 8; i++) {
        int rr = w + 8 * i;
        float s = ssq[i];
        #pragma unroll
        for (int o = 16; o; o >>= 1) s += __shfl_xor_sync(0xffffffffu, s, o);
        float r = rsqrtf(s * (1.0f / H) + 1e-6f);
        float v0 = r * s_l[rr][lane];
        float v1 = r * s_l[rr][lane + 32];
        float vals[4]; int ids[4];
        #pragma unroll
        for (int t4 = 0; t4 < 4; t4++) {
            float cv; int ci;
            if (v1 > v0) { cv = v1; ci = lane + 32; }
            else         { cv = v0; ci = lane; }   // tie -> smaller index
            #pragma unroll
            for (int o = 16; o; o >>= 1) {
                float ov = __shfl_xor_sync(0xffffffffu, cv, o);
                int   oi = __shfl_xor_sync(0xffffffffu, ci, o);
                if (ov > cv || (ov == cv && oi < ci)) { cv = ov; ci = oi; }
            }
            vals[t4] = cv; ids[t4] = ci;
            if (ci < 32) { if (lane == ci)      v0 = -3.4e38f; }
            else         { if (lane == ci - 32) v1 = -3.4e38f; }
        }
        if (lane == 0) {
            int row = bm * 64 + rr;
            float mmax = vals[0];
            float e0 = expf(vals[0] - mmax), e1 = expf(vals[1] - mmax);
            float e2 = expf(vals[2] - mmax), e3 = expf(vals[3] - mmax);
            float inv = 1.0f / (e0 + e1 + e2 + e3);
            float* ow = out + OFF_W + (size_t)row * 4;
            float* oi = out + OFF_I + (size_t)row * 4;
            ow[0] = e0 * inv; ow[1] = e1 * inv; ow[2] = e2 * inv; ow[3] = e3 * inv;
            oi[0] = (float)ids[0]; oi[1] = (float)ids[1];
            oi[2] = (float)ids[2]; oi[3] = (float)ids[3];
        }
    }
}

// ---------------------------------------------------------------------------
// K2: mask writer. 2048 blocks x 4 q-rows, interval predicates, plain stores.
// ---------------------------------------------------------------------------
__global__ __launch_bounds__(256) void mask_kernel(float* __restrict__ out) {
    int mb = blockIdx.x;                    // 0 .. 2047
    int b  = mb >> 10;
    int q0 = (mb & 1023) << 2;
    int tid = threadIdx.x;

    float* fullb = out + (size_t)b * S * S;
    float* slidb = out + OFF_SLID + (size_t)b * S * S;

    #pragma unroll
    for (int qi = 0; qi < 4; qi++) {
        int q = q0 + qi;
        int4 mt = g_qmeta[b * S + q];       // {flo, s1lo, v2lo, v2hi}
        int flo = mt.x, slo = mt.y, vlo = mt.z;
        unsigned vspan = (unsigned)(mt.w - mt.z);
        float4* fo = (float4*)(fullb + (size_t)q * S);
        float4* so = (float4*)(slidb + (size_t)q * S);
        #pragma unroll
        for (int it = 0; it < 4; it++) {
            int k4 = tid + it * 256;
            int kv = k4 * 4;
            float4 f, sl;
            #pragma unroll
            for (int j = 0; j < 4; j++) {
                int k = kv + j;
                bool fb = (k >= flo) & (k <= q);
                bool sb = ((k >= slo) & (k <= q)) | ((unsigned)(k - vlo) <= vspan);
                (&f.x)[j]  = fb ? 0.0f : NEGF;
                (&sl.x)[j] = sb ? 0.0f : NEGF;
            }
            fo[k4] = f;
            so[k4] = sl;
        }
    }
}

// ---------------------------------------------------------------------------
extern "C" void kernel_launch(void* const* d_in, const int* in_sizes, int n_in,
                              void* d_out, int out_size) {
    const float* x      = (const float*)d_in[0];
    const int*   packed = (const int*)d_in[1];
    const int*   mm     = (const int*)d_in[2];
    const float* scale  = (const float*)d_in[3];
    const float* pw     = (const float*)d_in[4];
    float* out = (float*)d_out;

    static int smem_set = 0;
    if (!smem_set) {
        cudaFuncSetAttribute(gate_kernel,
                             cudaFuncAttributeMaxDynamicSharedMemorySize,
                             GATE_SMEM_BYTES);
        smem_set = 1;
    }

    foldprep_kernel<<<FOLD_BLOCKS + B, 256>>>(scale, pw, packed, mm);
    gate_kernel<<<128, 256, GATE_SMEM_BYTES>>>(x, out);
    mask_kernel<<<2048, 256>>>(out);
}

// round 11
// speedup vs baseline: 1.7230x; 1.7230x over previous
#include <cuda_runtime.h>
#include <math.h>
#include <stdint.h>

#define H 2048
#define E 64
#define S 4096
#define B 2
#define SW 1024
#define NEGF (-3.4028234663852886e38f)   // -FLT_MAX == finfo(float32).min

#define OFF_SLID 33554432ull             // 2*4096*4096
#define OFF_W    67108864ull
#define OFF_I    67141632ull             // OFF_W + 8192*4

#define RSQRT_H 0.022097086912079608f    // 1/sqrt(2048)
#define KT 32                            // k-tile
#define PAD 68                           // row stride (floats) of k-major tiles
#define NKT (H / KT)                     // 64
#define TILE_F (KT * PAD)                // 2176 floats per W tile image
#define FOLD_BLOCKS 128

// scratch (no allocations allowed)
__device__ int4  g_qmeta[B * S];                       // {flo, s1lo, v2lo, v2hi}
__device__ __align__(16) float g_w2t[NKT * TILE_F];    // folded W, tile-image layout

// ---------------------------------------------------------------------------
// cp.async helpers
// ---------------------------------------------------------------------------
#define CP_ASYNC4(dst, src) \
    asm volatile("cp.async.ca.shared.global [%0], [%1], 4;" :: "r"(dst), "l"(src))
#define CP_ASYNC16(dst, src) \
    asm volatile("cp.async.cg.shared.global [%0], [%1], 16;" :: "r"(dst), "l"(src))
#define CP_COMMIT() asm volatile("cp.async.commit_group;")
#define CP_WAIT1()  asm volatile("cp.async.wait_group 1;")

// packed fp32x2 FMA (sm_100+), non-volatile so ptxas can schedule freely
__device__ __forceinline__ void ffma2(unsigned long long& d,
                                      unsigned long long a,
                                      unsigned long long b) {
    asm("fma.rn.f32x2 %0, %1, %2, %0;" : "+l"(d) : "l"(a), "l"(b));
}
__device__ __forceinline__ unsigned long long dup2(float v) {
    unsigned long long r;
    asm("mov.b64 %0,{%1,%1};" : "=l"(r) : "f"(v));
    return r;
}

// ---------------------------------------------------------------------------
// block-wide exclusive scans for prep (256 threads)
// ---------------------------------------------------------------------------
__device__ __forceinline__ int blk_excl_max(int agg, int t, int* sc) {
    int lane = t & 31, w = t >> 5;
    int inc = agg;
    #pragma unroll
    for (int o = 1; o < 32; o <<= 1) {
        int u = __shfl_up_sync(0xffffffffu, inc, o);
        if (lane >= o) inc = max(inc, u);
    }
    if (lane == 31) sc[w] = inc;
    __syncthreads();
    int wex = -0x7fffffff;
    for (int i = 0; i < w; i++) wex = max(wex, sc[i]);
    int lex = __shfl_up_sync(0xffffffffu, inc, 1);
    if (lane == 0) lex = -0x7fffffff;
    __syncthreads();
    return max(wex, lex);
}

__device__ __forceinline__ int blk_excl_min_bwd(int agg, int t, int* sc) {
    int lane = t & 31, w = t >> 5;
    int inc = agg;
    #pragma unroll
    for (int o = 1; o < 32; o <<= 1) {
        int u = __shfl_down_sync(0xffffffffu, inc, o);
        if (lane < 32 - o) inc = min(inc, u);
    }
    if (lane == 0) sc[w] = inc;
    __syncthreads();
    int wex = 0x7fffffff;
    for (int i = w + 1; i < 8; i++) wex = min(wex, sc[i]);
    int lex = __shfl_down_sync(0xffffffffu, inc, 1);
    if (lane == 31) lex = 0x7fffffff;
    __syncthreads();
    return min(wex, lex);
}

// ---------------------------------------------------------------------------
// K0: fold W into k-major tile images (+ 2 prep blocks for mask metadata)
// ---------------------------------------------------------------------------
__global__ __launch_bounds__(256) void foldprep_kernel(const float* __restrict__ scale,
                                                       const float* __restrict__ pw,
                                                       const int* __restrict__ packed,
                                                       const int* __restrict__ mm) {
    if (blockIdx.x < FOLD_BLOCKS) {
        int i = blockIdx.x * 1024 + threadIdx.x * 4;     // over E*H = 131072
        float4 pw4 = *(const float4*)(pw + i);
        float4 sc4 = *(const float4*)(scale + (i & (H - 1)));
        int e  = i >> 11;
        int h  = i & (H - 1);
        int kt = h >> 5, k = h & 31;                     // k % 4 == 0
        float* dst = g_w2t + kt * TILE_F + k * PAD + e;
        dst[0 * PAD] = pw4.x * sc4.x * RSQRT_H;
        dst[1 * PAD] = pw4.y * sc4.y * RSQRT_H;
        dst[2 * PAD] = pw4.z * sc4.z * RSQRT_H;
        dst[3 * PAD] = pw4.w * sc4.w * RSQRT_H;
    } else {
        // ================= PREP =================
        __shared__ int sc[8];
        const int INF = 0x7fffffff;
        int b = blockIdx.x - FOLD_BLOCKS;
        int t = threadIdx.x;
        int base = t * 16;
        const int* pk = packed + b * S;
        const int* m  = mm + b * S;

        int p[16]; bool v[16];
        #pragma unroll
        for (int c = 0; c < 4; c++) {
            int4 pp4 = ((const int4*)(pk + base))[c];
            int4 mm4 = ((const int4*)(m + base))[c];
            p[4*c+0] = pp4.x; p[4*c+1] = pp4.y; p[4*c+2] = pp4.z; p[4*c+3] = pp4.w;
            v[4*c+0] = (mm4.x == 1) | (mm4.x == 2);
            v[4*c+1] = (mm4.y == 1) | (mm4.y == 2);
            v[4*c+2] = (mm4.z == 1) | (mm4.z == 2);
            v[4*c+3] = (mm4.w == 1) | (mm4.w == 2);
        }
        int  pprev = (base > 0) ? pk[base - 1] : -123456;
        int  pnext = (base + 16 < S) ? pk[base + 16] : -123456;
        int  mprev = (base > 0) ? m[base - 1] : 0;
        int  mnext = (base + 16 < S) ? m[base + 16] : 0;
        bool vprev = (mprev == 1) | (mprev == 2);
        bool vnext = (mnext == 1) | (mnext == 2);

        int dloc[16];
        {
            int run = -1, pp = pprev;
            #pragma unroll
            for (int j = 0; j < 16; j++) {
                if (p[j] != pp) run = base + j;
                dloc[j] = run; pp = p[j];
            }
            int ex = blk_excl_max(run, t, sc);
            #pragma unroll
            for (int j = 0; j < 16; j++) if (ex > dloc[j]) dloc[j] = ex;
        }
        int vloc[16];
        {
            int run = -1; bool pv = vprev;
            #pragma unroll
            for (int j = 0; j < 16; j++) {
                if (v[j] && !pv) run = base + j;
                vloc[j] = run; pv = v[j];
            }
            int ex = blk_excl_max(run, t, sc);
            #pragma unroll
            for (int j = 0; j < 16; j++) if (ex > vloc[j]) vloc[j] = ex;
        }
        int dend[16];
        {
            int run = INF, np = pnext;
            #pragma unroll
            for (int jj = 15; jj >= 0; jj--) {
                if (p[jj] != np) run = base + jj;
                dend[jj] = run; np = p[jj];
            }
            int ex = blk_excl_min_bwd(run, t, sc);
            #pragma unroll
            for (int j = 0; j < 16; j++) if (ex < dend[j]) dend[j] = ex;
        }
        int vend[16];
        {
            int run = INF; bool nv = vnext;
            #pragma unroll
            for (int jj = 15; jj >= 0; jj--) {
                if (v[jj] && !nv) run = base + jj;
                vend[jj] = run; nv = v[jj];
            }
            int ex = blk_excl_min_bwd(run, t, sc);
            #pragma unroll
            for (int j = 0; j < 16; j++) if (ex < vend[j]) vend[j] = ex;
        }

        #pragma unroll
        for (int j = 0; j < 16; j++) {
            int q = base + j;
            int4 mt;
            if (p[j] <= 0) {
                mt.x = S; mt.y = S; mt.z = S; mt.w = -1;
            } else {
                int flo = dloc[j];
                mt.x = flo;
                int s1 = q - (SW - 1);
                mt.y = (s1 > flo) ? s1 : flo;
                if (v[j]) {
                    int vl = vloc[j]; if (flo > vl) vl = flo;
                    int vh = vend[j]; if (dend[j] < vh) vh = dend[j];
                    mt.z = vl; mt.w = vh;
                } else {
                    mt.z = S; mt.w = -1;
                }
            }
            g_qmeta[b * S + q] = mt;
        }
    }
}

// ---------------------------------------------------------------------------
// K1: gate. 128 blocks x (64 rows x 64 experts), cp.async 2-stage pipeline,
// FFMA2 with in-register X duplication (conflict-free LDS), fused RMS + top-4.
// ---------------------------------------------------------------------------
__global__ __launch_bounds__(256) void gate_kernel(const float* __restrict__ x,
                                                   float* __restrict__ out) {
    __shared__ union USm {
        struct { float X[2][KT][PAD]; float W[2][KT][PAD]; } p;   // 34816 B
        float s_l[64][PAD];
    } sm;

    int bm  = blockIdx.x;
    int tid = threadIdx.x;
    int w   = tid >> 5, lane = tid & 31;
    int tr  = tid >> 4, tc = tid & 15;
    const float* xb = x + (size_t)bm * 64 * H;

    uint32_t smb = (uint32_t)__cvta_generic_to_shared(&sm);
    const uint32_t XST = (uint32_t)(KT * PAD * 4);     // bytes per stage
    uint32_t wbase = smb + 2 * XST;

    int lrow = tid >> 5;
    int lk   = tid & 31;
    uint32_t xdst0 = smb + (uint32_t)(lk * PAD + lrow) * 4u;
    const float* xsrc0 = xb + (size_t)lrow * H + lk;

    // prologue: tile 0 into stage 0
    {
        #pragma unroll
        for (int i = 0; i < 8; i++)
            CP_ASYNC4(xdst0 + (uint32_t)(8 * i) * 4u, xsrc0 + (size_t)(8 * i) * H);
        const float4* wsrc = (const float4*)(g_w2t);
        CP_ASYNC16(wbase + (uint32_t)tid * 16u, wsrc + tid);
        CP_ASYNC16(wbase + (uint32_t)(tid + 256) * 16u, wsrc + tid + 256);
        if (tid < 32) CP_ASYNC16(wbase + (uint32_t)(tid + 512) * 16u, wsrc + tid + 512);
        CP_COMMIT();
    }

    unsigned long long acc[4][2] = {};   // [row i][expert pair]
    float ssq[8] = {};

    for (int kt = 0; kt < NKT; kt++) {
        int s = kt & 1;
        if (kt + 1 < NKT) {
            int ns = (kt + 1) & 1;
            uint32_t xd = xdst0 + (uint32_t)ns * XST;
            const float* xs = xsrc0 + (size_t)(kt + 1) * KT;
            #pragma unroll
            for (int i = 0; i < 8; i++)
                CP_ASYNC4(xd + (uint32_t)(8 * i) * 4u, xs + (size_t)(8 * i) * H);
            const float4* wsrc = (const float4*)(g_w2t + (size_t)(kt + 1) * TILE_F);
            uint32_t wd = wbase + (uint32_t)ns * XST;
            CP_ASYNC16(wd + (uint32_t)tid * 16u, wsrc + tid);
            CP_ASYNC16(wd + (uint32_t)(tid + 256) * 16u, wsrc + tid + 256);
            if (tid < 32) CP_ASYNC16(wd + (uint32_t)(tid + 512) * 16u, wsrc + tid + 512);
        }
        CP_COMMIT();
        CP_WAIT1();
        __syncthreads();

        #pragma unroll
        for (int k = 0; k < KT; k++) {
            float4 a = *(const float4*)&sm.p.X[s][k][4 * tr];
            ulonglong2 wv = *(const ulonglong2*)&sm.p.W[s][k][4 * tc];
            unsigned long long x0 = dup2(a.x), x1 = dup2(a.y);
            unsigned long long x2 = dup2(a.z), x3 = dup2(a.w);
            ffma2(acc[0][0], x0, wv.x); ffma2(acc[0][1], x0, wv.y);
            ffma2(acc[1][0], x1, wv.x); ffma2(acc[1][1], x1, wv.y);
            ffma2(acc[2][0], x2, wv.x); ffma2(acc[2][1], x2, wv.y);
            ffma2(acc[3][0], x3, wv.x); ffma2(acc[3][1], x3, wv.y);
        }
        // rms sum-of-squares pass (lane = k, rows w+8i)
        #pragma unroll
        for (int i = 0; i < 8; i++) {
            float v = sm.p.X[s][lane][w + 8 * i];
            ssq[i] = fmaf(v, v, ssq[i]);
        }
        __syncthreads();
    }

    // epilogue: logits to smem (aliases stage memory — pipeline done)
    #pragma unroll
    for (int i = 0; i < 4; i++) {
        #pragma unroll
        for (int pp = 0; pp < 2; pp++) {
            float lo, hi;
            asm("mov.b64 {%0,%1},%2;" : "=f"(lo), "=f"(hi) : "l"(acc[i][pp]));
            sm.s_l[4 * tr + i][4 * tc + 2 * pp]     = lo;
            sm.s_l[4 * tr + i][4 * tc + 2 * pp + 1] = hi;
        }
    }
    __syncthreads();

    // per-row top-4 + renormalized softmax (== softmax over top-4 logits)
    #pragma unroll
    for (int i = 0; i < 8; i++) {
        int rr = w + 8 * i;
        float s = ssq[i];
        #pragma unroll
        for (int o = 16; o; o >>= 1) s += __shfl_xor_sync(0xffffffffu, s, o);
        float r = rsqrtf(s * (1.0f / H) + 1e-6f);
        float v0 = r * sm.s_l[rr][lane];
        float v1 = r * sm.s_l[rr][lane + 32];
        float vals[4]; int ids[4];
        #pragma unroll
        for (int t4 = 0; t4 < 4; t4++) {
            float cv; int ci;
            if (v1 > v0) { cv = v1; ci = lane + 32; }
            else         { cv = v0; ci = lane; }   // tie -> smaller index
            #pragma unroll
            for (int o = 16; o; o >>= 1) {
                float ov = __shfl_xor_sync(0xffffffffu, cv, o);
                int   oi = __shfl_xor_sync(0xffffffffu, ci, o);
                if (ov > cv || (ov == cv && oi < ci)) { cv = ov; ci = oi; }
            }
            vals[t4] = cv; ids[t4] = ci;
            if (ci < 32) { if (lane == ci)      v0 = -3.4e38f; }
            else         { if (lane == ci - 32) v1 = -3.4e38f; }
        }
        if (lane == 0) {
            int row = bm * 64 + rr;
            float mmax = vals[0];
            float e0 = expf(vals[0] - mmax), e1 = expf(vals[1] - mmax);
            float e2 = expf(vals[2] - mmax), e3 = expf(vals[3] - mmax);
            float inv = 1.0f / (e0 + e1 + e2 + e3);
            float* ow = out + OFF_W + (size_t)row * 4;
            float* oi = out + OFF_I + (size_t)row * 4;
            ow[0] = e0 * inv; ow[1] = e1 * inv; ow[2] = e2 * inv; ow[3] = e3 * inv;
            oi[0] = (float)ids[0]; oi[1] = (float)ids[1];
            oi[2] = (float)ids[2]; oi[3] = (float)ids[3];
        }
    }
}

// ---------------------------------------------------------------------------
// K2: mask writer. 2048 blocks x 4 q-rows, interval predicates, plain stores.
// ---------------------------------------------------------------------------
__global__ __launch_bounds__(256) void mask_kernel(float* __restrict__ out) {
    int mb = blockIdx.x;                    // 0 .. 2047
    int b  = mb >> 10;
    int q0 = (mb & 1023) << 2;
    int tid = threadIdx.x;

    float* fullb = out + (size_t)b * S * S;
    float* slidb = out + OFF_SLID + (size_t)b * S * S;

    #pragma unroll
    for (int qi = 0; qi < 4; qi++) {
        int q = q0 + qi;
        int4 mt = g_qmeta[b * S + q];       // {flo, s1lo, v2lo, v2hi}
        int flo = mt.x, slo = mt.y, vlo = mt.z;
        unsigned vspan = (unsigned)(mt.w - mt.z);
        float4* fo = (float4*)(fullb + (size_t)q * S);
        float4* so = (float4*)(slidb + (size_t)q * S);
        #pragma unroll
        for (int it = 0; it < 4; it++) {
            int k4 = tid + it * 256;
            int kv = k4 * 4;
            float4 f, sl;
            #pragma unroll
            for (int j = 0; j < 4; j++) {
                int k = kv + j;
                bool fb = (k >= flo) & (k <= q);
                bool sb = ((k >= slo) & (k <= q)) | ((unsigned)(k - vlo) <= vspan);
                (&f.x)[j]  = fb ? 0.0f : NEGF;
                (&sl.x)[j] = sb ? 0.0f : NEGF;
            }
            fo[k4] = f;
            so[k4] = sl;
        }
    }
}

// ---------------------------------------------------------------------------
extern "C" void kernel_launch(void* const* d_in, const int* in_sizes, int n_in,
                              void* d_out, int out_size) {
    const float* x      = (const float*)d_in[0];
    const int*   packed = (const int*)d_in[1];
    const int*   mm     = (const int*)d_in[2];
    const float* scale  = (const float*)d_in[3];
    const float* pw     = (const float*)d_in[4];
    float* out = (float*)d_out;

    foldprep_kernel<<<FOLD_BLOCKS + B, 256>>>(scale, pw, packed, mm);
    gate_kernel<<<128, 256>>>(x, out);
    mask_kernel<<<2048, 256>>>(out);
}

// round 12
// speedup vs baseline: 1.7580x; 1.0203x over previous
#include <cuda_runtime.h>
#include <math.h>
#include <stdint.h>

#define H 2048
#define E 64
#define S 4096
#define B 2
#define SW 1024
#define NEGF (-3.4028234663852886e38f)   // -FLT_MAX == finfo(float32).min

#define OFF_SLID 33554432ull             // 2*4096*4096
#define OFF_W    67108864ull
#define OFF_I    67141632ull             // OFF_W + 8192*4

#define RSQRT_H 0.022097086912079608f    // 1/sqrt(2048)
#define KT 32                            // k-tile
#define PAD 68                           // row stride (floats) of k-major tiles
#define NKT (H / KT)                     // 64
#define TILE_F (KT * PAD)                // 2176 floats per tile image
#define GRP_F (4 * TILE_F)               // per-warpgroup smem region (X2 + W2)
#define GATE_SMEM_BYTES (2 * GRP_F * 4)  // 69632 B
#define GATE_BLOCKS 128

// scratch (no allocations allowed)
__device__ int4  g_qmeta[B * S];                       // {flo, s1lo, v2lo, v2hi}
__device__ __align__(16) float g_w2t[NKT * TILE_F];    // folded W, tile-image layout

// ---------------------------------------------------------------------------
// cp.async helpers
// ---------------------------------------------------------------------------
#define CP_ASYNC4(dst, src) \
    asm volatile("cp.async.ca.shared.global [%0], [%1], 4;" :: "r"(dst), "l"(src))
#define CP_ASYNC16(dst, src) \
    asm volatile("cp.async.cg.shared.global [%0], [%1], 16;" :: "r"(dst), "l"(src))
#define CP_COMMIT() asm volatile("cp.async.commit_group;")
#define CP_WAIT1()  asm volatile("cp.async.wait_group 1;")

// packed fp32x2 FMA (sm_100+)
__device__ __forceinline__ void ffma2(unsigned long long& d,
                                      unsigned long long a,
                                      unsigned long long b) {
    asm("fma.rn.f32x2 %0, %1, %2, %0;" : "+l"(d) : "l"(a), "l"(b));
}
__device__ __forceinline__ unsigned long long dup2(float v) {
    unsigned long long r;
    asm("mov.b64 %0,{%1,%1};" : "=l"(r) : "f"(v));
    return r;
}

// ---------------------------------------------------------------------------
// K0: fold scale & H^-0.5 into W, k-major tile-image layout
// ---------------------------------------------------------------------------
__global__ __launch_bounds__(256) void fold_kernel(const float* __restrict__ scale,
                                                   const float* __restrict__ pw) {
    int i = blockIdx.x * 1024 + threadIdx.x * 4;     // over E*H = 131072
    float4 pw4 = *(const float4*)(pw + i);
    float4 sc4 = *(const float4*)(scale + (i & (H - 1)));
    int e  = i >> 11;
    int h  = i & (H - 1);
    int kt = h >> 5, k = h & 31;                     // k % 4 == 0
    float* dst = g_w2t + kt * TILE_F + k * PAD + e;
    dst[0 * PAD] = pw4.x * sc4.x * RSQRT_H;
    dst[1 * PAD] = pw4.y * sc4.y * RSQRT_H;
    dst[2 * PAD] = pw4.z * sc4.z * RSQRT_H;
    dst[3 * PAD] = pw4.w * sc4.w * RSQRT_H;
}

// ---------------------------------------------------------------------------
// 512-thread block scans for prep (16 warps, 8 elems/thread)
// ---------------------------------------------------------------------------
__device__ __forceinline__ int blk_excl_max512(int agg, int t, int* sc) {
    int lane = t & 31, w = t >> 5;
    int inc = agg;
    #pragma unroll
    for (int o = 1; o < 32; o <<= 1) {
        int u = __shfl_up_sync(0xffffffffu, inc, o);
        if (lane >= o) inc = max(inc, u);
    }
    if (lane == 31) sc[w] = inc;
    __syncthreads();
    int wex = -0x7fffffff;
    for (int i = 0; i < w; i++) wex = max(wex, sc[i]);
    int lex = __shfl_up_sync(0xffffffffu, inc, 1);
    if (lane == 0) lex = -0x7fffffff;
    __syncthreads();
    return max(wex, lex);
}

__device__ __forceinline__ int blk_excl_min_bwd512(int agg, int t, int* sc) {
    int lane = t & 31, w = t >> 5;
    int inc = agg;
    #pragma unroll
    for (int o = 1; o < 32; o <<= 1) {
        int u = __shfl_down_sync(0xffffffffu, inc, o);
        if (lane < 32 - o) inc = min(inc, u);
    }
    if (lane == 0) sc[w] = inc;
    __syncthreads();
    int wex = 0x7fffffff;
    for (int i = w + 1; i < 16; i++) wex = min(wex, sc[i]);
    int lex = __shfl_down_sync(0xffffffffu, inc, 1);
    if (lane == 31) lex = 0x7fffffff;
    __syncthreads();
    return min(wex, lex);
}

// ---------------------------------------------------------------------------
// K1: blocks [0,128): split-K gate (warpgroup 0: K[0:1024], wg 1: K[1024:2048])
//     blocks [128,130): prep (mask interval metadata) on otherwise-idle SMs
// ---------------------------------------------------------------------------
__global__ __launch_bounds__(512) void gate_prep_kernel(const float* __restrict__ x,
                                                        const int* __restrict__ packed,
                                                        const int* __restrict__ mm,
                                                        float* __restrict__ out) {
    extern __shared__ __align__(16) float dsm[];
    __shared__ float ssq2[64];
    __shared__ int sc[16];

    int tid = threadIdx.x;

    if (blockIdx.x < GATE_BLOCKS) {
        // ================= GATE (split-K) =================
        int g = tid >> 8;                 // warpgroup: 0 or 1
        int t = tid & 255;
        int w = t >> 5, lane = t & 31;
        int tr = t >> 4, tc = t & 15;
        const float* xb = x + (size_t)blockIdx.x * 64 * H;

        float* grp = dsm + g * GRP_F;     // X stages [0,2*TILE_F), W stages after
        uint32_t gbase = (uint32_t)__cvta_generic_to_shared(grp);
        const uint32_t XST = (uint32_t)(TILE_F * 4);
        uint32_t wbase = gbase + 2 * XST;

        uint32_t xdst0 = gbase + (uint32_t)(lane * PAD + w) * 4u;
        const float* xsrc0 = xb + (size_t)w * H + g * (H / 2) + lane;
        const float* wimg = g_w2t + (size_t)g * (NKT / 2) * TILE_F;

        // prologue: local tile 0 into stage 0
        {
            #pragma unroll
            for (int i = 0; i < 8; i++)
                CP_ASYNC4(xdst0 + (uint32_t)(8 * i) * 4u, xsrc0 + (size_t)(8 * i) * H);
            const float4* wsrc = (const float4*)(wimg);
            CP_ASYNC16(wbase + (uint32_t)t * 16u, wsrc + t);
            CP_ASYNC16(wbase + (uint32_t)(t + 256) * 16u, wsrc + t + 256);
            if (t < 32) CP_ASYNC16(wbase + (uint32_t)(t + 512) * 16u, wsrc + t + 512);
            CP_COMMIT();
        }

        unsigned long long acc[4][2] = {};
        float ssq[8] = {};

        for (int kt = 0; kt < NKT / 2; kt++) {
            int s = kt & 1;
            if (kt + 1 < NKT / 2) {
                int ns = (kt + 1) & 1;
                uint32_t xd = xdst0 + (uint32_t)ns * XST;
                const float* xs = xsrc0 + (size_t)(kt + 1) * KT;
                #pragma unroll
                for (int i = 0; i < 8; i++)
                    CP_ASYNC4(xd + (uint32_t)(8 * i) * 4u, xs + (size_t)(8 * i) * H);
                const float4* wsrc = (const float4*)(wimg + (size_t)(kt + 1) * TILE_F);
                uint32_t wd = wbase + (uint32_t)ns * XST;
                CP_ASYNC16(wd + (uint32_t)t * 16u, wsrc + t);
                CP_ASYNC16(wd + (uint32_t)(t + 256) * 16u, wsrc + t + 256);
                if (t < 32) CP_ASYNC16(wd + (uint32_t)(t + 512) * 16u, wsrc + t + 512);
            }
            CP_COMMIT();
            CP_WAIT1();
            __syncthreads();

            const float* Xs = grp + s * TILE_F;
            const float* Ws = grp + (2 + s) * TILE_F;
            #pragma unroll
            for (int k = 0; k < KT; k++) {
                float4 a = *(const float4*)(Xs + k * PAD + 4 * tr);
                ulonglong2 wv = *(const ulonglong2*)(Ws + k * PAD + 4 * tc);
                unsigned long long x0 = dup2(a.x), x1 = dup2(a.y);
                unsigned long long x2 = dup2(a.z), x3 = dup2(a.w);
                ffma2(acc[0][0], x0, wv.x); ffma2(acc[0][1], x0, wv.y);
                ffma2(acc[1][0], x1, wv.x); ffma2(acc[1][1], x1, wv.y);
                ffma2(acc[2][0], x2, wv.x); ffma2(acc[2][1], x2, wv.y);
                ffma2(acc[3][0], x3, wv.x); ffma2(acc[3][1], x3, wv.y);
            }
            // rms sum-of-squares pass (lane = k, rows w+8i) over this K half
            #pragma unroll
            for (int i = 0; i < 8; i++) {
                float v = Xs[lane * PAD + (w + 8 * i)];
                ssq[i] = fmaf(v, v, ssq[i]);
            }
            __syncthreads();
        }

        // write this group's partial logits into its X region (pipeline done)
        float (*s_lg)[PAD] = (float (*)[PAD])grp;
        #pragma unroll
        for (int i = 0; i < 4; i++) {
            #pragma unroll
            for (int pp = 0; pp < 2; pp++) {
                float lo, hi;
                asm("mov.b64 {%0,%1},%2;" : "=f"(lo), "=f"(hi) : "l"(acc[i][pp]));
                s_lg[4 * tr + i][4 * tc + 2 * pp]     = lo;
                s_lg[4 * tr + i][4 * tc + 2 * pp + 1] = hi;
            }
        }
        // group 1 publishes its per-row ssq partials
        if (g == 1) {
            #pragma unroll
            for (int i = 0; i < 8; i++) {
                float s = ssq[i];
                #pragma unroll
                for (int o = 16; o; o >>= 1) s += __shfl_xor_sync(0xffffffffu, s, o);
                if (lane == 0) ssq2[w + 8 * i] = s;
            }
        }
        __syncthreads();

        if (g == 0) {
            float (*s_l1)[PAD] = (float (*)[PAD])(dsm + GRP_F);
            #pragma unroll
            for (int i = 0; i < 8; i++) {
                int rr = w + 8 * i;
                float s = ssq[i];
                #pragma unroll
                for (int o = 16; o; o >>= 1) s += __shfl_xor_sync(0xffffffffu, s, o);
                s += ssq2[rr];
                float r = rsqrtf(s * (1.0f / H) + 1e-6f);
                float v0 = r * (s_lg[rr][lane]      + s_l1[rr][lane]);
                float v1 = r * (s_lg[rr][lane + 32] + s_l1[rr][lane + 32]);
                float vals[4]; int ids[4];
                #pragma unroll
                for (int t4 = 0; t4 < 4; t4++) {
                    float cv; int ci;
                    if (v1 > v0) { cv = v1; ci = lane + 32; }
                    else         { cv = v0; ci = lane; }   // tie -> smaller index
                    #pragma unroll
                    for (int o = 16; o; o >>= 1) {
                        float ov = __shfl_xor_sync(0xffffffffu, cv, o);
                        int   oi = __shfl_xor_sync(0xffffffffu, ci, o);
                        if (ov > cv || (ov == cv && oi < ci)) { cv = ov; ci = oi; }
                    }
                    vals[t4] = cv; ids[t4] = ci;
                    if (ci < 32) { if (lane == ci)      v0 = -3.4e38f; }
                    else         { if (lane == ci - 32) v1 = -3.4e38f; }
                }
                if (lane == 0) {
                    int row = blockIdx.x * 64 + rr;
                    float mmax = vals[0];
                    float e0 = expf(vals[0] - mmax), e1 = expf(vals[1] - mmax);
                    float e2 = expf(vals[2] - mmax), e3 = expf(vals[3] - mmax);
                    float inv = 1.0f / (e0 + e1 + e2 + e3);
                    float* ow = out + OFF_W + (size_t)row * 4;
                    float* oi = out + OFF_I + (size_t)row * 4;
                    ow[0] = e0 * inv; ow[1] = e1 * inv; ow[2] = e2 * inv; ow[3] = e3 * inv;
                    oi[0] = (float)ids[0]; oi[1] = (float)ids[1];
                    oi[2] = (float)ids[2]; oi[3] = (float)ids[3];
                }
            }
        }
    } else {
        // ================= PREP (512 threads, 8 elems/thread) =================
        const int INF = 0x7fffffff;
        int b = blockIdx.x - GATE_BLOCKS;
        int t = tid;
        int base = t * 8;
        const int* pk = packed + b * S;
        const int* m  = mm + b * S;

        int p[8]; bool v[8];
        #pragma unroll
        for (int c = 0; c < 2; c++) {
            int4 pp4 = ((const int4*)(pk + base))[c];
            int4 mm4 = ((const int4*)(m + base))[c];
            p[4*c+0] = pp4.x; p[4*c+1] = pp4.y; p[4*c+2] = pp4.z; p[4*c+3] = pp4.w;
            v[4*c+0] = (mm4.x == 1) | (mm4.x == 2);
            v[4*c+1] = (mm4.y == 1) | (mm4.y == 2);
            v[4*c+2] = (mm4.z == 1) | (mm4.z == 2);
            v[4*c+3] = (mm4.w == 1) | (mm4.w == 2);
        }
        int  pprev = (base > 0) ? pk[base - 1] : -123456;
        int  pnext = (base + 8 < S) ? pk[base + 8] : -123456;
        int  mprev = (base > 0) ? m[base - 1] : 0;
        int  mnext = (base + 8 < S) ? m[base + 8] : 0;
        bool vprev = (mprev == 1) | (mprev == 2);
        bool vnext = (mnext == 1) | (mnext == 2);

        int dloc[8];
        {
            int run = -1, pp = pprev;
            #pragma unroll
            for (int j = 0; j < 8; j++) {
                if (p[j] != pp) run = base + j;
                dloc[j] = run; pp = p[j];
            }
            int ex = blk_excl_max512(run, t, sc);
            #pragma unroll
            for (int j = 0; j < 8; j++) if (ex > dloc[j]) dloc[j] = ex;
        }
        int vloc[8];
        {
            int run = -1; bool pv = vprev;
            #pragma unroll
            for (int j = 0; j < 8; j++) {
                if (v[j] && !pv) run = base + j;
                vloc[j] = run; pv = v[j];
            }
            int ex = blk_excl_max512(run, t, sc);
            #pragma unroll
            for (int j = 0; j < 8; j++) if (ex > vloc[j]) vloc[j] = ex;
        }
        int dend[8];
        {
            int run = INF, np = pnext;
            #pragma unroll
            for (int jj = 7; jj >= 0; jj--) {
                if (p[jj] != np) run = base + jj;
                dend[jj] = run; np = p[jj];
            }
            int ex = blk_excl_min_bwd512(run, t, sc);
            #pragma unroll
            for (int j = 0; j < 8; j++) if (ex < dend[j]) dend[j] = ex;
        }
        int vend[8];
        {
            int run = INF; bool nv = vnext;
            #pragma unroll
            for (int jj = 7; jj >= 0; jj--) {
                if (v[jj] && !nv) run = base + jj;
                vend[jj] = run; nv = v[jj];
            }
            int ex = blk_excl_min_bwd512(run, t, sc);
            #pragma unroll
            for (int j = 0; j < 8; j++) if (ex < vend[j]) vend[j] = ex;
        }

        #pragma unroll
        for (int j = 0; j < 8; j++) {
            int q = base + j;
            int4 mt;
            if (p[j] <= 0) {
                mt.x = S; mt.y = S; mt.z = S; mt.w = -1;
            } else {
                int flo = dloc[j];
                mt.x = flo;
                int s1 = q - (SW - 1);
                mt.y = (s1 > flo) ? s1 : flo;
                if (v[j]) {
                    int vl = vloc[j]; if (flo > vl) vl = flo;
                    int vh = vend[j]; if (dend[j] < vh) vh = dend[j];
                    mt.z = vl; mt.w = vh;
                } else {
                    mt.z = S; mt.w = -1;
                }
            }
            g_qmeta[b * S + q] = mt;
        }
    }
}

// ---------------------------------------------------------------------------
// K2: mask writer. 2048 blocks x 4 q-rows, interval predicates, plain stores.
// ---------------------------------------------------------------------------
__global__ __launch_bounds__(256) void mask_kernel(float* __restrict__ out) {
    int mb = blockIdx.x;                    // 0 .. 2047
    int b  = mb >> 10;
    int q0 = (mb & 1023) << 2;
    int tid = threadIdx.x;

    float* fullb = out + (size_t)b * S * S;
    float* slidb = out + OFF_SLID + (size_t)b * S * S;

    #pragma unroll
    for (int qi = 0; qi < 4; qi++) {
        int q = q0 + qi;
        int4 mt = g_qmeta[b * S + q];       // {flo, s1lo, v2lo, v2hi}
        int flo = mt.x, slo = mt.y, vlo = mt.z;
        unsigned vspan = (unsigned)(mt.w - mt.z);
        float4* fo = (float4*)(fullb + (size_t)q * S);
        float4* so = (float4*)(slidb + (size_t)q * S);
        #pragma unroll
        for (int it = 0; it < 4; it++) {
            int k4 = tid + it * 256;
            int kv = k4 * 4;
            float4 f, sl;
            #pragma unroll
            for (int j = 0; j < 4; j++) {
                int k = kv + j;
                bool fb = (k >= flo) & (k <= q);
                bool sb = ((k >= slo) & (k <= q)) | ((unsigned)(k - vlo) <= vspan);
                (&f.x)[j]  = fb ? 0.0f : NEGF;
                (&sl.x)[j] = sb ? 0.0f : NEGF;
            }
            fo[k4] = f;
            so[k4] = sl;
        }
    }
}

// ---------------------------------------------------------------------------
extern "C" void kernel_launch(void* const* d_in, const int* in_sizes, int n_in,
                              void* d_out, int out_size) {
    const float* x      = (const float*)d_in[0];
    const int*   packed = (const int*)d_in[1];
    const int*   mm     = (const int*)d_in[2];
    const float* scale  = (const float*)d_in[3];
    const float* pw     = (const float*)d_in[4];
    float* out = (float*)d_out;

    static int smem_set = 0;
    if (!smem_set) {
        cudaFuncSetAttribute(gate_prep_kernel,
                             cudaFuncAttributeMaxDynamicSharedMemorySize,
                             GATE_SMEM_BYTES);
        smem_set = 1;
    }

    fold_kernel<<<128, 256>>>(scale, pw);
    gate_prep_kernel<<<GATE_BLOCKS + B, 512, GATE_SMEM_BYTES>>>(x, packed, mm, out);
    mask_kernel<<<2048, 256>>>(out);
}